// round 2
// baseline (speedup 1.0000x reference)
#include <cuda_runtime.h>
#include <cstdint>

// out[b,i,j] = x[b, i, i+j] if i+j < L else 0
// B=4, L=4096, LIMIT=256
#define MAXLEN 4096
#define LIMIT  256
#define BATCH  4

// total float4 outputs = 4*4096*64 = 1,048,576
#define TOTAL_V4   (BATCH * MAXLEN * (LIMIT / 4))
#define VPT        4                        // float4s per thread
#define NTHREADS   (TOTAL_V4 / VPT)         // 262,144
#define TPB        256
#define NBLOCKS    (NTHREADS / TPB)         // 1024

__global__ __launch_bounds__(TPB)
void band_gather_kernel(const float* __restrict__ x, float* __restrict__ out)
{
    const int gid = blockIdx.x * TPB + threadIdx.x;

    // 4 independent output groups, grid-strided so every STG.128 is
    // perfectly coalesced (consecutive lanes -> consecutive float4s).
    int   idx[VPT];
    const float* srcp[VPT];
    int   c0v[VPT];

    #pragma unroll
    for (int k = 0; k < VPT; k++) {
        const int id  = gid + k * NTHREADS;
        const int row = id >> 6;             // /64 float4s per band row
        const int j0  = (id & 63) << 2;      // j within band
        const int i   = row & (MAXLEN - 1);  // row within matrix
        idx[k]  = id;
        srcp[k] = x + ((size_t)row << 12);   // row * 4096
        c0v[k]  = i + j0;
    }

    // Issue all 16 loads before any store (max MLP).
    float4 v[VPT];
    #pragma unroll
    for (int k = 0; k < VPT; k++) {
        const float* s = srcp[k];
        const int c0 = c0v[k];
        v[k].x = (c0 + 0 < MAXLEN) ? __ldcs(s + c0 + 0) : 0.0f;
        v[k].y = (c0 + 1 < MAXLEN) ? __ldcs(s + c0 + 1) : 0.0f;
        v[k].z = (c0 + 2 < MAXLEN) ? __ldcs(s + c0 + 2) : 0.0f;
        v[k].w = (c0 + 3 < MAXLEN) ? __ldcs(s + c0 + 3) : 0.0f;
    }

    #pragma unroll
    for (int k = 0; k < VPT; k++) {
        __stcs(reinterpret_cast<float4*>(out) + idx[k], v[k]);
    }
}

extern "C" void kernel_launch(void* const* d_in, const int* in_sizes, int n_in,
                              void* d_out, int out_size)
{
    (void)in_sizes; (void)n_in; (void)out_size;
    const float* x = (const float*)d_in[0];
    float* out = (float*)d_out;
    band_gather_kernel<<<NBLOCKS, TPB>>>(x, out);
}

// round 3
// speedup vs baseline: 1.0036x; 1.0036x over previous
#include <cuda_runtime.h>
#include <cstdint>

// out[b,i,j] = x[b, i, i+j] if i+j < L else 0
// B=4, L=4096, LIMIT=256
#define MAXLEN 4096
#define LIMIT  256
#define BATCH  4

#define TOTAL_ELEMS (BATCH * MAXLEN * LIMIT)   // 4,194,304
#define EPT         8                           // elements per thread
#define NTHREADS    (TOTAL_ELEMS / EPT)         // 524,288
#define TPB         256
#define NBLOCKS     (NTHREADS / TPB)            // 2048

__global__ __launch_bounds__(TPB)
void band_gather_kernel(const float* __restrict__ x, float* __restrict__ out)
{
    const int gid = blockIdx.x * TPB + threadIdx.x;

    // Scalar mapping: element e -> (row = e>>8, j = e&255).
    // Consecutive lanes -> consecutive j -> consecutive source AND dest
    // addresses => every LDG.32 / STG.32 is a single 128B wavefront.
    float v[EPT];
    int   ide[EPT];

    #pragma unroll
    for (int k = 0; k < EPT; k++) {
        const int id  = gid + k * NTHREADS;
        const int j   = id & (LIMIT - 1);
        const int row = id >> 8;                 // b*L + i
        const int i   = row & (MAXLEN - 1);
        const int c   = i + j;
        ide[k] = id;
        v[k] = (c < MAXLEN) ? __ldg(x + ((size_t)row << 12) + c) : 0.0f;
    }

    #pragma unroll
    for (int k = 0; k < EPT; k++) {
        out[ide[k]] = v[k];
    }
}

extern "C" void kernel_launch(void* const* d_in, const int* in_sizes, int n_in,
                              void* d_out, int out_size)
{
    (void)in_sizes; (void)n_in; (void)out_size;
    const float* x = (const float*)d_in[0];
    float* out = (float*)d_out;
    band_gather_kernel<<<NBLOCKS, TPB>>>(x, out);
}

// round 4
// speedup vs baseline: 1.0294x; 1.0257x over previous
#include <cuda_runtime.h>
#include <cstdint>

// out[b,i,j] = x[b, i, i+j] if i+j < L else 0
// B=4, L=4096, LIMIT=256
#define MAXLEN 4096
#define LIMIT  256
#define BATCH  4

#define NROWS      (BATCH * MAXLEN)   // 16384 band rows
#define WARPS_PB   8
#define TPB        (WARPS_PB * 32)    // 256
#define NBLOCKS    (NROWS / WARPS_PB) // 2048

__global__ __launch_bounds__(TPB)
void band_gather_kernel(const float* __restrict__ x, float* __restrict__ out)
{
    const int warp = (blockIdx.x * WARPS_PB) + (threadIdx.x >> 5);
    const int lane = threadIdx.x & 31;

    const int row = warp;                    // b*L + i
    const int i   = row & (MAXLEN - 1);
    const int a   = i & 3;                   // misalignment, warp-uniform
    const int bc4 = i >> 2;                  // first aligned f4 block in row
    const float4* __restrict__ xr =
        reinterpret_cast<const float4*>(x) + ((size_t)row << 10); // row*1024 f4
    float4* __restrict__ orow =
        reinterpret_cast<float4*>(out) + ((size_t)row << 6);      // row*64 f4
    const int lim = MAXLEN - i;              // j < lim is valid

    // Two output f4s per lane: o = lane and o = lane+32.
    // Each needs aligned source blocks (bc4+o) and (bc4+o+1), clamped to row end.
    float4 w0a, w1a, w0b, w1b;
    {
        const int q0a = min(bc4 + lane,      1023);
        const int q1a = min(bc4 + lane + 1,  1023);
        const int q0b = min(bc4 + lane + 32, 1023);
        const int q1b = min(bc4 + lane + 33, 1023);
        w0a = __ldg(xr + q0a);
        w1a = __ldg(xr + q1a);
        w0b = __ldg(xr + q0b);
        w1b = __ldg(xr + q1b);
    }

    #pragma unroll
    for (int it = 0; it < 2; it++) {
        const int o = lane + it * 32;        // output f4 index (0..63)
        float4 w0 = it ? w0b : w0a;
        float4 w1 = it ? w1b : w1a;

        // funnel shift by 'a' floats (warp-uniform branch)
        float4 v;
        if      (a == 0) { v.x = w0.x; v.y = w0.y; v.z = w0.z; v.w = w0.w; }
        else if (a == 1) { v.x = w0.y; v.y = w0.z; v.z = w0.w; v.w = w1.x; }
        else if (a == 2) { v.x = w0.z; v.y = w0.w; v.z = w1.x; v.w = w1.y; }
        else             { v.x = w0.w; v.y = w1.x; v.z = w1.y; v.w = w1.z; }

        // zero past the row edge: j = 4*o + k must be < lim
        const int j0 = o << 2;
        if (j0 + 3 >= lim) {                 // rare tail rows only
            if (j0 + 0 >= lim) v.x = 0.0f;
            if (j0 + 1 >= lim) v.y = 0.0f;
            if (j0 + 2 >= lim) v.z = 0.0f;
            if (j0 + 3 >= lim) v.w = 0.0f;
        }

        orow[o] = v;
    }
}

extern "C" void kernel_launch(void* const* d_in, const int* in_sizes, int n_in,
                              void* d_out, int out_size)
{
    (void)in_sizes; (void)n_in; (void)out_size;
    const float* x = (const float*)d_in[0];
    float* out = (float*)d_out;
    band_gather_kernel<<<NBLOCKS, TPB>>>(x, out);
}